// round 12
// baseline (speedup 1.0000x reference)
#include <cuda_runtime.h>
#include <cuda_fp16.h>
#include <mma.h>
#include <cstdint>
using namespace nvcuda;

#define B_  256
#define W_  256
#define D_  1024
#define K_  32
#define NRB_ 8
#define ALPHA_ 0.9f

// ---- scratch ----
__device__ __half  g_Ah  [B_*K_*D_];   // 16 MB  fp16 of m_k*(C@x)
__device__ __half  g_Wch [D_*D_];      //  2 MB  compress_W fp16 (as-is, [e,d])
__device__ __half  g_Rwh [D_*D_];      //  2 MB  retrieve_W fp16 (as-is, [e,d])
__device__ float   g_rA  [B_*D_];      //  1 MB  sum_k U2*A
__device__ __half  g_retrh[B_*D_];     // fp16 retr
__device__ float   g_retr2[B_*D_];
__device__ float   g_m[K_];
__device__ float   g_U2[K_*D_];
__device__ float   g_U3[K_*D_];
__device__ float   g_base[D_];
__device__ float   g_sout;

__device__ __forceinline__ float sigmoidf_(float v) { return 1.0f / (1.0f + expf(-v)); }

__device__ __forceinline__ void cpa16(void* smem, const void* gmem) {
    unsigned sa = (unsigned)__cvta_generic_to_shared(smem);
    asm volatile("cp.async.cg.shared.global [%0], [%1], 16;\n" :: "r"(sa), "l"(gmem));
}
__device__ __forceinline__ void cpa_commit() { asm volatile("cp.async.commit_group;\n"); }
__device__ __forceinline__ void cpa_wait0() { asm volatile("cp.async.wait_group 0;\n"); }
__device__ __forceinline__ void cpa_wait1() { asm volatile("cp.async.wait_group 1;\n"); }
__device__ __forceinline__ void cpa_wait3() { asm volatile("cp.async.wait_group 3;\n"); }

// ---- K0: scalars, m_k, U2/U3 tables, base ----------------------------------
__global__ void k_prep(const float* wb, const float* fb, const float* ig,
                       const float* bg, const float* cg, const float* bt,
                       const float* rr, const float* ri, const float* sig,
                       const float* Vmr, const float* Vmi) {
    int e = threadIdx.x;  // 1024
    float gc = sigmoidf_(cg[0]);
    if (e < K_) {
        float scale = (e == 0 ? 1.0f : 2.0f) / (float)W_;
        g_m[e] = scale * sig[e] * (wb[e] + fb[e]);
    }
    if (e == 0) g_sout = sigmoidf_(ig[0]) * bg[0];
    float sr = 0.f, si = 0.f;
    #pragma unroll
    for (int k = 0; k < NRB_; k++) {
        float tr = sigmoidf_(bt[k]);
        sr += tr * rr[k * D_ + e];
        si += tr * ri[k * D_ + e];
    }
    g_base[e] = ALPHA_ * (sr * Vmr[e] + si * Vmi[e]);
    float c2 = (1.0f - ALPHA_) * (1.0f - gc);
    float c3 = (1.0f - ALPHA_) * gc;
    #pragma unroll
    for (int k = 0; k < K_; k++) {
        float U = sr * rr[k * D_ + e] + si * ri[k * D_ + e];
        g_U2[k * D_ + e] = c2 * U;
        g_U3[k * D_ + e] = c3 * U;
    }
}

// ---- K0b: elementwise fp16 casts --------------------------------------------
__global__ void k_cast(const float* __restrict__ Wc, const float* __restrict__ Rw) {
    size_t i = (size_t)blockIdx.x * blockDim.x + threadIdx.x;  // float4 granule
    float4 w = ((const float4*)Wc)[i];
    float4 r = ((const float4*)Rw)[i];
    __half2* wd = (__half2*)&g_Wch[i * 4];
    __half2* rd = (__half2*)&g_Rwh[i * 4];
    wd[0] = __floats2half2_rn(w.x, w.y);
    wd[1] = __floats2half2_rn(w.z, w.w);
    rd[0] = __floats2half2_rn(r.x, r.y);
    rd[1] = __floats2half2_rn(r.z, r.w);
}

// ---- K1: tf32 tensor cheby, 4-deep 16-row pipeline --------------------------
#define CH_DT 256
#define CH_LD 264
#define CH_NS 4
__global__ __launch_bounds__(256) void k_cheby(const float* __restrict__ x,
                                               const float* __restrict__ C) {
    extern __shared__ float sh[];
    float* sC = sh;                      // [32][CH_LD]
    float* xs = sh + 32 * CH_LD;         // CH_NS x [16][CH_LD]
    __shared__ float sm[K_];
    int tid = threadIdx.x;
    int wid = tid >> 5;
    int b   = blockIdx.y;
    int d0  = blockIdx.x * CH_DT;
    const float* xb = x + (size_t)b * W_ * D_ + d0;

    auto load_chunk = [&](int c) {
        float* dst = xs + (c & (CH_NS - 1)) * 16 * CH_LD;
        const float* src = xb + (size_t)c * 16 * D_;
        #pragma unroll
        for (int i = 0; i < 4; i++) {
            int idx = i * 256 + tid;          // 0..1023 16B segs
            int r = idx >> 6, seg = idx & 63; // row 0..15
            cpa16(dst + r * CH_LD + seg * 4, src + (size_t)r * D_ + seg * 4);
        }
        cpa_commit();
    };

    load_chunk(0);
    load_chunk(1);
    load_chunk(2);

    for (int i = tid; i < K_ * W_; i += 256)
        sC[(i >> 8) * CH_LD + (i & 255)] = C[i];
    if (tid < K_) sm[tid] = g_m[tid];

    wmma::fragment<wmma::accumulator, 16, 16, 8, float> acc[2][2];
    #pragma unroll
    for (int i = 0; i < 2; i++)
        #pragma unroll
        for (int j = 0; j < 2; j++) wmma::fill_fragment(acc[i][j], 0.0f);

    for (int c = 0; c < 16; c++) {
        __syncthreads();                 // all warps done with buffer (c+3)&3
        if (c + 3 < 16) load_chunk(c + 3);
        else cpa_commit();               // empty group keeps count arithmetic
        cpa_wait3();                     // 4 pending -> oldest (chunk c) done
        __syncthreads();
        float* xc = xs + (c & (CH_NS - 1)) * 16 * CH_LD;
        #pragma unroll
        for (int ks = 0; ks < 2; ks++) {
            wmma::fragment<wmma::matrix_a, 16, 16, 8, wmma::precision::tf32, wmma::row_major> af[2];
            wmma::fragment<wmma::matrix_b, 16, 16, 8, wmma::precision::tf32, wmma::row_major> bf[2];
            #pragma unroll
            for (int i = 0; i < 2; i++)
                wmma::load_matrix_sync(af[i], &sC[(i * 16) * CH_LD + c * 16 + ks * 8], CH_LD);
            #pragma unroll
            for (int j = 0; j < 2; j++)
                wmma::load_matrix_sync(bf[j], &xc[(ks * 8) * CH_LD + wid * 32 + j * 16], CH_LD);
            #pragma unroll
            for (int i = 0; i < 2; i++)
                #pragma unroll
                for (int j = 0; j < 2; j++)
                    wmma::mma_sync(acc[i][j], af[i], bf[j], acc[i][j]);
        }
    }
    __syncthreads();

    float* sA = sh;
    #pragma unroll
    for (int i = 0; i < 2; i++)
        #pragma unroll
        for (int j = 0; j < 2; j++)
            wmma::store_matrix_sync(&sA[(i * 16) * CH_LD + wid * 32 + j * 16],
                                    acc[i][j], CH_LD, wmma::mem_row_major);
    __syncthreads();
    int dg = d0 + tid;
    float rA = 0.f;
    size_t abase = ((size_t)b * K_) * D_ + dg;
    #pragma unroll
    for (int k = 0; k < K_; k++) {
        float v = sm[k] * sA[k * CH_LD + tid];
        rA += g_U2[k * D_ + dg] * v;
        g_Ah[abase + (size_t)k * D_] = __float2half(v);
    }
    g_rA[(size_t)b * D_ + dg] = rA;
}

// ---- K2: G = Ah @ Wch^T (fp16 accum), warp tile 64x64, block 128x256 ---------
// R8-proven ordering: load(it+1) -> wait -> sync -> compute -> sync.
#define GM 128
#define GN 256
#define GK 32
#define ALD 40   // 32 + 8 pad (halves)
#define BLD 40
#define SLD 264
__global__ __launch_bounds__(256, 2) void k_gemm() {
    extern __shared__ char shg[];
    __half* As = (__half*)shg;                                   // 2 x [128][ALD]
    __half* Bs = (__half*)(shg + 2 * GM * ALD * sizeof(__half)); // 2 x [256][BLD]
    __half* Sgh = (__half*)shg;                                   // epi [128][SLD]
    int tid = threadIdx.x;
    int wid = tid >> 5;
    int wm = wid >> 2, wn = wid & 3;  // 2x4 warps, warp tile 64(m) x 64(n)
    size_t m0 = (size_t)blockIdx.y * GM;
    size_t n0 = (size_t)blockIdx.x * GN;

    wmma::fragment<wmma::accumulator, 16, 16, 16, __half> acc[4][4];
    #pragma unroll
    for (int i = 0; i < 4; i++)
        #pragma unroll
        for (int j = 0; j < 4; j++) wmma::fill_fragment(acc[i][j], __float2half(0.0f));

    // per stage: A 128x32 halves = 512 segs, B 256x32 halves = 1024 segs
    auto load_stage = [&](int it) {
        int s = it & 1;
        const __half* Ag = &g_Ah [m0 * D_ + (size_t)it * GK];
        const __half* Bg = &g_Wch[n0 * D_ + (size_t)it * GK];
        __half* Ad = &As[s * GM * ALD];
        __half* Bd = &Bs[s * GN * BLD];
        #pragma unroll
        for (int i = 0; i < 2; i++) {
            int idx = i * 256 + tid;          // 0..511
            int r = idx >> 2, seg = idx & 3;  // row 0..127, 16B seg 0..3
            cpa16(Ad + r * ALD + seg * 8, Ag + (size_t)r * D_ + seg * 8);
        }
        #pragma unroll
        for (int i = 0; i < 4; i++) {
            int idx = i * 256 + tid;          // 0..1023
            int r = idx >> 2, seg = idx & 3;  // row 0..255
            cpa16(Bd + r * BLD + seg * 8, Bg + (size_t)r * D_ + seg * 8);
        }
        cpa_commit();
    };

    load_stage(0);

    const int NIT = D_ / GK;  // 32
    for (int it = 0; it < NIT; it++) {
        if (it < NIT - 1) {
            load_stage(it + 1);
            cpa_wait1();
        } else {
            cpa_wait0();
        }
        __syncthreads();
        int s = it & 1;
        const __half* Ab = &As[s * GM * ALD];
        const __half* Bb = &Bs[s * GN * BLD];
        #pragma unroll
        for (int ks = 0; ks < 2; ks++) {
            wmma::fragment<wmma::matrix_a, 16, 16, 16, __half, wmma::row_major> af[4];
            wmma::fragment<wmma::matrix_b, 16, 16, 16, __half, wmma::col_major> bf[4];
            #pragma unroll
            for (int i = 0; i < 4; i++)
                wmma::load_matrix_sync(af[i], &Ab[(wm * 64 + i * 16) * ALD + ks * 16], ALD);
            #pragma unroll
            for (int j = 0; j < 4; j++)
                wmma::load_matrix_sync(bf[j], &Bb[(wn * 64 + j * 16) * BLD + ks * 16], BLD);
            #pragma unroll
            for (int i = 0; i < 4; i++)
                #pragma unroll
                for (int j = 0; j < 4; j++)
                    wmma::mma_sync(acc[i][j], af[i], bf[j], acc[i][j]);
        }
        __syncthreads();
    }

    // epilogue: G tile (fp16) -> smem, reduce over k with U3, emit retr
    #pragma unroll
    for (int i = 0; i < 4; i++)
        #pragma unroll
        for (int j = 0; j < 4; j++)
            wmma::store_matrix_sync(
                &Sgh[(wm * 64 + i * 16) * SLD + wn * 64 + j * 16],
                acc[i][j], SLD, wmma::mem_row_major);
    __syncthreads();
    int e  = tid;               // 0..255 (e col within tile)
    int eg = (int)n0 + e;
    #pragma unroll
    for (int b4 = 0; b4 < 4; b4++) {
        float sacc = 0.f;
        #pragma unroll
        for (int k = 0; k < K_; k++)
            sacc += g_U3[k * D_ + eg] * __half2float(Sgh[(b4 * 32 + k) * SLD + e]);
        int bg = (int)(m0 >> 5) + b4;
        g_retrh[(size_t)bg * D_ + eg] =
            __float2half(g_base[eg] + g_rA[(size_t)bg * D_ + eg] + sacc);
    }
}

// ---- K4: retr2 = retrh @ Rwh^T, GM=64 tiles (32 blocks), R8 proven -----------
#define G2M 64
#define G2N 128
#define G2K 64
#define A2LD 72
#define B2LD 72
__global__ __launch_bounds__(256) void k_gemm2() {
    extern __shared__ char shg[];
    __half* As = (__half*)shg;                                     // 2 x [64][A2LD]
    __half* Bs = (__half*)(shg + 2 * G2M * A2LD * sizeof(__half)); // 2 x [128][B2LD]
    int tid = threadIdx.x;
    int wid = tid >> 5;
    int wm = wid >> 1, wn = wid & 1;  // 4(m) x 2(n), warp tile 16 x 64
    size_t m0 = (size_t)blockIdx.y * G2M;
    size_t n0 = (size_t)blockIdx.x * G2N;

    wmma::fragment<wmma::accumulator, 16, 16, 16, float> acc[4];
    #pragma unroll
    for (int j = 0; j < 4; j++) wmma::fill_fragment(acc[j], 0.0f);

    auto load_stage = [&](int it) {
        int s = it & 1;
        const __half* Ag = &g_retrh[m0 * D_ + (size_t)it * G2K];
        const __half* Bg = &g_Rwh  [n0 * D_ + (size_t)it * G2K];
        __half* Ad = &As[s * G2M * A2LD];
        __half* Bd = &Bs[s * G2N * B2LD];
        #pragma unroll
        for (int i = 0; i < 2; i++) {
            int idx = i * 256 + tid;          // 0..511
            int r = idx >> 3, seg = idx & 7;  // row 0..63
            cpa16(Ad + r * A2LD + seg * 8, Ag + (size_t)r * D_ + seg * 8);
        }
        #pragma unroll
        for (int i = 0; i < 4; i++) {
            int idx = i * 256 + tid;
            int r = idx >> 3, seg = idx & 7;
            cpa16(Bd + r * B2LD + seg * 8, Bg + (size_t)r * D_ + seg * 8);
        }
        cpa_commit();
    };

    load_stage(0);

    for (int it = 0; it < D_ / G2K; it++) {
        if (it < D_ / G2K - 1) {
            load_stage(it + 1);
            cpa_wait1();
        } else {
            cpa_wait0();
        }
        __syncthreads();
        int s = it & 1;
        const __half* Ab = &As[s * G2M * A2LD];
        const __half* Bb = &Bs[s * G2N * B2LD];
        #pragma unroll
        for (int ks = 0; ks < 4; ks++) {
            wmma::fragment<wmma::matrix_a, 16, 16, 16, __half, wmma::row_major> af;
            wmma::fragment<wmma::matrix_b, 16, 16, 16, __half, wmma::col_major> bf[4];
            wmma::load_matrix_sync(af, &Ab[(wm * 16) * A2LD + ks * 16], A2LD);
            #pragma unroll
            for (int j = 0; j < 4; j++)
                wmma::load_matrix_sync(bf[j], &Bb[(wn * 64 + j * 16) * B2LD + ks * 16], B2LD);
            #pragma unroll
            for (int j = 0; j < 4; j++)
                wmma::mma_sync(acc[j], af, bf[j], acc[j]);
        }
        __syncthreads();
    }

    #pragma unroll
    for (int j = 0; j < 4; j++)
        wmma::store_matrix_sync(
            &g_retr2[(m0 + wm * 16) * D_ + n0 + wn * 64 + j * 16],
            acc[j], D_, wmma::mem_row_major);
}

// ---- K5: out = x + s * retr2 ---------------------------------------------------
__global__ void k_out(const float* __restrict__ x, float* __restrict__ out) {
    size_t i4 = (size_t)blockIdx.x * blockDim.x + threadIdx.x;
    int d4 = (int)(i4 & (D_ / 4 - 1));
    size_t bw = i4 >> 8;
    int b = (int)(bw >> 8);
    float s = g_sout;
    float4 xv = ((const float4*)x)[i4];
    float4 rv = ((const float4*)g_retr2)[(size_t)b * (D_ / 4) + d4];
    float4 o;
    o.x = xv.x + s * rv.x;
    o.y = xv.y + s * rv.y;
    o.z = xv.z + s * rv.z;
    o.w = xv.w + s * rv.w;
    ((float4*)out)[i4] = o;
}

extern "C" void kernel_launch(void* const* d_in, const int* in_sizes, int n_in,
                              void* d_out, int out_size) {
    const float* x   = (const float*)d_in[0];
    const float* wb  = (const float*)d_in[1];
    const float* fb  = (const float*)d_in[2];
    const float* ig  = (const float*)d_in[3];
    const float* bg  = (const float*)d_in[4];
    const float* cg  = (const float*)d_in[5];
    const float* bt  = (const float*)d_in[6];
    const float* Wc  = (const float*)d_in[7];
    const float* Rw  = (const float*)d_in[8];
    const float* rr  = (const float*)d_in[9];
    const float* ri  = (const float*)d_in[10];
    const float* Vmr = (const float*)d_in[11];
    const float* Vmi = (const float*)d_in[12];
    const float* C   = (const float*)d_in[13];
    const float* sig = (const float*)d_in[14];
    float* out = (float*)d_out;

    const int cheby_smem = (32 + CH_NS * 16) * CH_LD * 4;                        // 101376
    const int gemm_pipe  = 2 * (GM * ALD + GN * BLD) * (int)sizeof(__half);      // 61440
    const int gemm_epi   = GM * SLD * (int)sizeof(__half);                       // 67584
    const int gemm_smem  = gemm_pipe > gemm_epi ? gemm_pipe : gemm_epi;          // 67584
    const int gemm2_smem = 2 * (G2M * A2LD + G2N * B2LD) * (int)sizeof(__half);  // 55296
    static bool attr_set = false;
    if (!attr_set) {
        cudaFuncSetAttribute(k_cheby, cudaFuncAttributeMaxDynamicSharedMemorySize,
                             cheby_smem);
        cudaFuncSetAttribute(k_gemm, cudaFuncAttributeMaxDynamicSharedMemorySize,
                             gemm_smem);
        cudaFuncSetAttribute(k_gemm2, cudaFuncAttributeMaxDynamicSharedMemorySize,
                             gemm2_smem);
        attr_set = true;
    }

    k_prep<<<1, 1024>>>(wb, fb, ig, bg, cg, bt, rr, ri, sig, Vmr, Vmi);
    k_cast<<<(D_ * D_ / 4) / 256, 256>>>(Wc, Rw);
    k_cheby<<<dim3(D_ / CH_DT, B_), 256, cheby_smem>>>(x, C);
    k_gemm<<<dim3(D_ / GN, (B_ * K_) / GM), 256, gemm_smem>>>();
    k_gemm2<<<dim3(D_ / G2N, B_ / G2M), 256, gemm2_smem>>>();
    k_out<<<(B_ * W_ * D_ / 4) / 256, 256>>>(x, out);
}

// round 13
// speedup vs baseline: 1.0339x; 1.0339x over previous
#include <cuda_runtime.h>
#include <cuda_fp16.h>
#include <mma.h>
#include <cstdint>
using namespace nvcuda;

#define B_  256
#define W_  256
#define D_  1024
#define K_  32
#define NRB_ 8
#define ALPHA_ 0.9f

// ---- scratch ----
__device__ __half  g_Ah  [B_*K_*D_];   // 16 MB  fp16 of m_k*(C@x)
__device__ __half  g_Wch [D_*D_];      //  2 MB  compress_W fp16 (as-is, [e,d])
__device__ __half  g_Rwh [D_*D_];      //  2 MB  retrieve_W fp16 (as-is, [e,d])
__device__ float   g_rA  [B_*D_];      //  1 MB  sum_k U2*A
__device__ __half  g_retrh[B_*D_];     // fp16 retr
__device__ float   g_retr2[B_*D_];
__device__ float   g_m[K_];
__device__ float   g_U2[K_*D_];
__device__ float   g_U3[K_*D_];
__device__ float   g_base[D_];
__device__ float   g_sout;

__device__ __forceinline__ float sigmoidf_(float v) { return 1.0f / (1.0f + expf(-v)); }

__device__ __forceinline__ void cpa16(void* smem, const void* gmem) {
    unsigned sa = (unsigned)__cvta_generic_to_shared(smem);
    asm volatile("cp.async.cg.shared.global [%0], [%1], 16;\n" :: "r"(sa), "l"(gmem));
}
__device__ __forceinline__ void cpa_commit() { asm volatile("cp.async.commit_group;\n"); }
__device__ __forceinline__ void cpa_wait0() { asm volatile("cp.async.wait_group 0;\n"); }
__device__ __forceinline__ void cpa_wait1() { asm volatile("cp.async.wait_group 1;\n"); }
__device__ __forceinline__ void cpa_wait3() { asm volatile("cp.async.wait_group 3;\n"); }

// ---- K0: scalars, m_k, U2/U3 tables, base ----------------------------------
__global__ void k_prep(const float* wb, const float* fb, const float* ig,
                       const float* bg, const float* cg, const float* bt,
                       const float* rr, const float* ri, const float* sig,
                       const float* Vmr, const float* Vmi) {
    int e = threadIdx.x;  // 1024
    float gc = sigmoidf_(cg[0]);
    if (e < K_) {
        float scale = (e == 0 ? 1.0f : 2.0f) / (float)W_;
        g_m[e] = scale * sig[e] * (wb[e] + fb[e]);
    }
    if (e == 0) g_sout = sigmoidf_(ig[0]) * bg[0];
    float sr = 0.f, si = 0.f;
    #pragma unroll
    for (int k = 0; k < NRB_; k++) {
        float tr = sigmoidf_(bt[k]);
        sr += tr * rr[k * D_ + e];
        si += tr * ri[k * D_ + e];
    }
    g_base[e] = ALPHA_ * (sr * Vmr[e] + si * Vmi[e]);
    float c2 = (1.0f - ALPHA_) * (1.0f - gc);
    float c3 = (1.0f - ALPHA_) * gc;
    #pragma unroll
    for (int k = 0; k < K_; k++) {
        float U = sr * rr[k * D_ + e] + si * ri[k * D_ + e];
        g_U2[k * D_ + e] = c2 * U;
        g_U3[k * D_ + e] = c3 * U;
    }
}

// ---- K0b: elementwise fp16 casts --------------------------------------------
__global__ void k_cast(const float* __restrict__ Wc, const float* __restrict__ Rw) {
    size_t i = (size_t)blockIdx.x * blockDim.x + threadIdx.x;  // float4 granule
    float4 w = ((const float4*)Wc)[i];
    float4 r = ((const float4*)Rw)[i];
    __half2* wd = (__half2*)&g_Wch[i * 4];
    __half2* rd = (__half2*)&g_Rwh[i * 4];
    wd[0] = __floats2half2_rn(w.x, w.y);
    wd[1] = __floats2half2_rn(w.z, w.w);
    rd[0] = __floats2half2_rn(r.x, r.y);
    rd[1] = __floats2half2_rn(r.z, r.w);
}

// ---- K1: tf32 tensor cheby, 4-deep 16-row pipeline --------------------------
#define CH_DT 256
#define CH_LD 264
#define CH_NS 4
__global__ __launch_bounds__(256) void k_cheby(const float* __restrict__ x,
                                               const float* __restrict__ C) {
    extern __shared__ float sh[];
    float* sC = sh;                      // [32][CH_LD]
    float* xs = sh + 32 * CH_LD;         // CH_NS x [16][CH_LD]
    __shared__ float sm[K_];
    int tid = threadIdx.x;
    int wid = tid >> 5;
    int b   = blockIdx.y;
    int d0  = blockIdx.x * CH_DT;
    const float* xb = x + (size_t)b * W_ * D_ + d0;

    auto load_chunk = [&](int c) {
        float* dst = xs + (c & (CH_NS - 1)) * 16 * CH_LD;
        const float* src = xb + (size_t)c * 16 * D_;
        #pragma unroll
        for (int i = 0; i < 4; i++) {
            int idx = i * 256 + tid;          // 0..1023 16B segs
            int r = idx >> 6, seg = idx & 63; // row 0..15
            cpa16(dst + r * CH_LD + seg * 4, src + (size_t)r * D_ + seg * 4);
        }
        cpa_commit();
    };

    load_chunk(0);
    load_chunk(1);
    load_chunk(2);

    for (int i = tid; i < K_ * W_; i += 256)
        sC[(i >> 8) * CH_LD + (i & 255)] = C[i];
    if (tid < K_) sm[tid] = g_m[tid];

    wmma::fragment<wmma::accumulator, 16, 16, 8, float> acc[2][2];
    #pragma unroll
    for (int i = 0; i < 2; i++)
        #pragma unroll
        for (int j = 0; j < 2; j++) wmma::fill_fragment(acc[i][j], 0.0f);

    for (int c = 0; c < 16; c++) {
        __syncthreads();                 // all warps done with buffer (c+3)&3
        if (c + 3 < 16) load_chunk(c + 3);
        else cpa_commit();               // empty group keeps count arithmetic
        cpa_wait3();                     // 4 pending -> oldest (chunk c) done
        __syncthreads();
        float* xc = xs + (c & (CH_NS - 1)) * 16 * CH_LD;
        #pragma unroll
        for (int ks = 0; ks < 2; ks++) {
            wmma::fragment<wmma::matrix_a, 16, 16, 8, wmma::precision::tf32, wmma::row_major> af[2];
            wmma::fragment<wmma::matrix_b, 16, 16, 8, wmma::precision::tf32, wmma::row_major> bf[2];
            #pragma unroll
            for (int i = 0; i < 2; i++)
                wmma::load_matrix_sync(af[i], &sC[(i * 16) * CH_LD + c * 16 + ks * 8], CH_LD);
            #pragma unroll
            for (int j = 0; j < 2; j++)
                wmma::load_matrix_sync(bf[j], &xc[(ks * 8) * CH_LD + wid * 32 + j * 16], CH_LD);
            #pragma unroll
            for (int i = 0; i < 2; i++)
                #pragma unroll
                for (int j = 0; j < 2; j++)
                    wmma::mma_sync(acc[i][j], af[i], bf[j], acc[i][j]);
        }
    }
    __syncthreads();

    float* sA = sh;
    #pragma unroll
    for (int i = 0; i < 2; i++)
        #pragma unroll
        for (int j = 0; j < 2; j++)
            wmma::store_matrix_sync(&sA[(i * 16) * CH_LD + wid * 32 + j * 16],
                                    acc[i][j], CH_LD, wmma::mem_row_major);
    __syncthreads();
    int dg = d0 + tid;
    float rA = 0.f;
    size_t abase = ((size_t)b * K_) * D_ + dg;
    #pragma unroll
    for (int k = 0; k < K_; k++) {
        float v = sm[k] * sA[k * CH_LD + tid];
        rA += g_U2[k * D_ + dg] * v;
        g_Ah[abase + (size_t)k * D_] = __float2half(v);
    }
    g_rA[(size_t)b * D_ + dg] = rA;
}

// ---- K2: G = Ah @ Wch^T (fp16 accum), R6/R8 proven config, fused U3 epi ------
#define GM 128
#define GN 128
#define GK 64
#define ALD 72
#define BLD 72
#define SLD 136
__global__ __launch_bounds__(256) void k_gemm() {
    extern __shared__ char shg[];
    __half* As = (__half*)shg;                                   // 2 x [128][ALD]
    __half* Bs = (__half*)(shg + 2 * GM * ALD * sizeof(__half)); // 2 x [128][BLD]
    __half* Sgh = (__half*)shg;                                   // epi [128][SLD]
    int tid = threadIdx.x;
    int wid = tid >> 5;
    int wm = wid >> 1, wn = wid & 1;  // 4x2 warps, warp tile 32(m) x 64(n)
    size_t m0 = (size_t)blockIdx.y * GM;
    size_t n0 = (size_t)blockIdx.x * GN;

    wmma::fragment<wmma::accumulator, 16, 16, 16, __half> acc[2][4];
    #pragma unroll
    for (int i = 0; i < 2; i++)
        #pragma unroll
        for (int j = 0; j < 4; j++) wmma::fill_fragment(acc[i][j], __float2half(0.0f));

    auto load_stage = [&](int it) {
        int s = it & 1;
        const __half* Ag = &g_Ah [m0 * D_ + (size_t)it * GK];
        const __half* Bg = &g_Wch[n0 * D_ + (size_t)it * GK];
        __half* Ad = &As[s * GM * ALD];
        __half* Bd = &Bs[s * GN * BLD];
        #pragma unroll
        for (int i = 0; i < 4; i++) {
            int idx = i * 256 + tid;
            int r = idx >> 3, seg = idx & 7;
            cpa16(Ad + r * ALD + seg * 8, Ag + (size_t)r * D_ + seg * 8);
        }
        #pragma unroll
        for (int i = 0; i < 4; i++) {
            int idx = i * 256 + tid;
            int r = idx >> 3, seg = idx & 7;
            cpa16(Bd + r * BLD + seg * 8, Bg + (size_t)r * D_ + seg * 8);
        }
        cpa_commit();
    };

    load_stage(0);

    for (int it = 0; it < D_ / GK; it++) {
        if (it < D_ / GK - 1) {
            load_stage(it + 1);
            cpa_wait1();
        } else {
            cpa_wait0();
        }
        __syncthreads();
        int s = it & 1;
        const __half* Ab = &As[s * GM * ALD];
        const __half* Bb = &Bs[s * GN * BLD];
        #pragma unroll
        for (int ks = 0; ks < 4; ks++) {
            wmma::fragment<wmma::matrix_a, 16, 16, 16, __half, wmma::row_major> af[2];
            wmma::fragment<wmma::matrix_b, 16, 16, 16, __half, wmma::col_major> bf[4];
            #pragma unroll
            for (int i = 0; i < 2; i++)
                wmma::load_matrix_sync(af[i], &Ab[(wm * 32 + i * 16) * ALD + ks * 16], ALD);
            #pragma unroll
            for (int j = 0; j < 4; j++)
                wmma::load_matrix_sync(bf[j], &Bb[(wn * 64 + j * 16) * BLD + ks * 16], BLD);
            #pragma unroll
            for (int i = 0; i < 2; i++)
                #pragma unroll
                for (int j = 0; j < 4; j++)
                    wmma::mma_sync(acc[i][j], af[i], bf[j], acc[i][j]);
        }
        __syncthreads();
    }

    #pragma unroll
    for (int i = 0; i < 2; i++)
        #pragma unroll
        for (int j = 0; j < 4; j++)
            wmma::store_matrix_sync(&Sgh[(wm * 32 + i * 16) * SLD + wn * 64 + j * 16],
                                    acc[i][j], SLD, wmma::mem_row_major);
    __syncthreads();
    int e  = tid & 127;
    int bh = tid >> 7;
    int eg = (int)n0 + e;
    #pragma unroll
    for (int ob = 0; ob < 2; ob++) {
        int b4 = ob * 2 + bh;
        float sacc = 0.f;
        #pragma unroll
        for (int k = 0; k < K_; k++)
            sacc += g_U3[k * D_ + eg] * __half2float(Sgh[(b4 * 32 + k) * SLD + e]);
        int bg = (int)(m0 >> 5) + b4;
        g_retrh[(size_t)bg * D_ + eg] =
            __float2half(g_base[eg] + g_rA[(size_t)bg * D_ + eg] + sacc);
    }
}

// ---- K4: retr2 = retrh @ Rwh^T, GM=64 tiles (32 blocks), R8 proven -----------
#define G2M 64
#define G2N 128
#define G2K 64
#define A2LD 72
#define B2LD 72
__global__ __launch_bounds__(256) void k_gemm2() {
    extern __shared__ char shg[];
    __half* As = (__half*)shg;                                     // 2 x [64][A2LD]
    __half* Bs = (__half*)(shg + 2 * G2M * A2LD * sizeof(__half)); // 2 x [128][B2LD]
    int tid = threadIdx.x;
    int wid = tid >> 5;
    int wm = wid >> 1, wn = wid & 1;  // 4(m) x 2(n), warp tile 16 x 64
    size_t m0 = (size_t)blockIdx.y * G2M;
    size_t n0 = (size_t)blockIdx.x * G2N;

    wmma::fragment<wmma::accumulator, 16, 16, 16, float> acc[4];
    #pragma unroll
    for (int j = 0; j < 4; j++) wmma::fill_fragment(acc[j], 0.0f);

    auto load_stage = [&](int it) {
        int s = it & 1;
        const __half* Ag = &g_retrh[m0 * D_ + (size_t)it * G2K];
        const __half* Bg = &g_Rwh  [n0 * D_ + (size_t)it * G2K];
        __half* Ad = &As[s * G2M * A2LD];
        __half* Bd = &Bs[s * G2N * B2LD];
        #pragma unroll
        for (int i = 0; i < 2; i++) {
            int idx = i * 256 + tid;          // 0..511
            int r = idx >> 3, seg = idx & 7;  // row 0..63
            cpa16(Ad + r * A2LD + seg * 8, Ag + (size_t)r * D_ + seg * 8);
        }
        #pragma unroll
        for (int i = 0; i < 4; i++) {
            int idx = i * 256 + tid;
            int r = idx >> 3, seg = idx & 7;
            cpa16(Bd + r * B2LD + seg * 8, Bg + (size_t)r * D_ + seg * 8);
        }
        cpa_commit();
    };

    load_stage(0);

    for (int it = 0; it < D_ / G2K; it++) {
        if (it < D_ / G2K - 1) {
            load_stage(it + 1);
            cpa_wait1();
        } else {
            cpa_wait0();
        }
        __syncthreads();
        int s = it & 1;
        const __half* Ab = &As[s * G2M * A2LD];
        const __half* Bb = &Bs[s * G2N * B2LD];
        #pragma unroll
        for (int ks = 0; ks < 4; ks++) {
            wmma::fragment<wmma::matrix_a, 16, 16, 16, __half, wmma::row_major> af;
            wmma::fragment<wmma::matrix_b, 16, 16, 16, __half, wmma::col_major> bf[4];
            wmma::load_matrix_sync(af, &Ab[(wm * 16) * A2LD + ks * 16], A2LD);
            #pragma unroll
            for (int j = 0; j < 4; j++)
                wmma::load_matrix_sync(bf[j], &Bb[(wn * 64 + j * 16) * B2LD + ks * 16], B2LD);
            #pragma unroll
            for (int j = 0; j < 4; j++)
                wmma::mma_sync(acc[j], af, bf[j], acc[j]);
        }
        __syncthreads();
    }

    #pragma unroll
    for (int j = 0; j < 4; j++)
        wmma::store_matrix_sync(
            &g_retr2[(m0 + wm * 16) * D_ + n0 + wn * 64 + j * 16],
            acc[j], D_, wmma::mem_row_major);
}

// ---- K5: out = x + s * retr2; each thread does rows (b,w) and (b,w+128) ------
__global__ void k_out(const float* __restrict__ x, float* __restrict__ out) {
    size_t t = (size_t)blockIdx.x * blockDim.x + threadIdx.x;  // 0 .. B*W/2*D/4
    int d4 = (int)(t & (D_ / 4 - 1));
    size_t rest = t >> 8;            // / (D_/4)
    int w = (int)(rest & (W_ / 2 - 1));
    int b = (int)(rest >> 7);        // / (W_/2)
    float s = g_sout;
    float4 rv = __ldg(&((const float4*)g_retr2)[(size_t)b * (D_ / 4) + d4]);
    size_t i4a = ((size_t)(b * W_ + w) * (D_ / 4)) + d4;
    size_t i4b = i4a + (size_t)(W_ / 2) * (D_ / 4);
    float4 xa = __ldcs(&((const float4*)x)[i4a]);
    float4 xb = __ldcs(&((const float4*)x)[i4b]);
    float4 oa, ob;
    oa.x = xa.x + s * rv.x; oa.y = xa.y + s * rv.y;
    oa.z = xa.z + s * rv.z; oa.w = xa.w + s * rv.w;
    ob.x = xb.x + s * rv.x; ob.y = xb.y + s * rv.y;
    ob.z = xb.z + s * rv.z; ob.w = xb.w + s * rv.w;
    __stcs(&((float4*)out)[i4a], oa);
    __stcs(&((float4*)out)[i4b], ob);
}

extern "C" void kernel_launch(void* const* d_in, const int* in_sizes, int n_in,
                              void* d_out, int out_size) {
    const float* x   = (const float*)d_in[0];
    const float* wb  = (const float*)d_in[1];
    const float* fb  = (const float*)d_in[2];
    const float* ig  = (const float*)d_in[3];
    const float* bg  = (const float*)d_in[4];
    const float* cg  = (const float*)d_in[5];
    const float* bt  = (const float*)d_in[6];
    const float* Wc  = (const float*)d_in[7];
    const float* Rw  = (const float*)d_in[8];
    const float* rr  = (const float*)d_in[9];
    const float* ri  = (const float*)d_in[10];
    const float* Vmr = (const float*)d_in[11];
    const float* Vmi = (const float*)d_in[12];
    const float* C   = (const float*)d_in[13];
    const float* sig = (const float*)d_in[14];
    float* out = (float*)d_out;

    const int cheby_smem = (32 + CH_NS * 16) * CH_LD * 4;                        // 101376
    const int gemm_smem  = 2 * (GM * ALD + GN * BLD) * (int)sizeof(__half);      // 73728
    const int gemm2_smem = 2 * (G2M * A2LD + G2N * B2LD) * (int)sizeof(__half);  // 55296

    static cudaStream_t s_side = nullptr;
    static cudaEvent_t ev_fork = nullptr, ev_join = nullptr;
    static bool init_done = false;
    if (!init_done) {
        cudaFuncSetAttribute(k_cheby, cudaFuncAttributeMaxDynamicSharedMemorySize,
                             cheby_smem);
        cudaFuncSetAttribute(k_gemm, cudaFuncAttributeMaxDynamicSharedMemorySize,
                             gemm_smem);
        cudaFuncSetAttribute(k_gemm2, cudaFuncAttributeMaxDynamicSharedMemorySize,
                             gemm2_smem);
        cudaStreamCreateWithFlags(&s_side, cudaStreamNonBlocking);
        cudaEventCreateWithFlags(&ev_fork, cudaEventDisableTiming);
        cudaEventCreateWithFlags(&ev_join, cudaEventDisableTiming);
        init_done = true;
    }

    // fork: k_cast is independent of prep/cheby
    cudaEventRecord(ev_fork, 0);
    cudaStreamWaitEvent(s_side, ev_fork, 0);
    k_cast<<<(D_ * D_ / 4) / 256, 256, 0, s_side>>>(Wc, Rw);
    cudaEventRecord(ev_join, s_side);

    k_prep<<<1, 1024>>>(wb, fb, ig, bg, cg, bt, rr, ri, sig, Vmr, Vmi);
    k_cheby<<<dim3(D_ / CH_DT, B_), 256, cheby_smem>>>(x, C);

    // join before the GEMMs (they consume g_Wch / g_Rwh)
    cudaStreamWaitEvent(0, ev_join, 0);
    k_gemm<<<dim3(D_ / GN, (B_ * K_) / GM), 256, gemm_smem>>>();
    k_gemm2<<<dim3(D_ / G2N, B_ / G2M), 256, gemm2_smem>>>();
    k_out<<<(B_ * W_ * D_ / 8) / 256, 256>>>(x, out);
}

// round 14
// speedup vs baseline: 1.0400x; 1.0059x over previous
#include <cuda_runtime.h>
#include <cuda_fp16.h>
#include <mma.h>
#include <cstdint>
using namespace nvcuda;

#define B_  256
#define W_  256
#define D_  1024
#define K_  32
#define NRB_ 8
#define ALPHA_ 0.9f

// ---- scratch ----
__device__ __half  g_Ah  [B_*K_*D_];   // 16 MB  fp16 of m_k*(C@x)
__device__ __half  g_Wch [D_*D_];      //  2 MB  compress_W fp16 (as-is, [e,d])
__device__ __half  g_Rwh [D_*D_];      //  2 MB  retrieve_W fp16 (as-is, [e,d])
__device__ float   g_rA  [B_*D_];      //  1 MB  sum_k U2*A
__device__ __half  g_retrh[B_*D_];     // fp16 retr
__device__ float   g_retr2[B_*D_];
__device__ float   g_m[K_];
__device__ float   g_U2[K_*D_];
__device__ float   g_U3[K_*D_];
__device__ float   g_base[D_];
__device__ float   g_sout;

__device__ __forceinline__ float sigmoidf_(float v) { return 1.0f / (1.0f + expf(-v)); }

__device__ __forceinline__ void cpa16(void* smem, const void* gmem) {
    unsigned sa = (unsigned)__cvta_generic_to_shared(smem);
    asm volatile("cp.async.cg.shared.global [%0], [%1], 16;\n" :: "r"(sa), "l"(gmem));
}
__device__ __forceinline__ void cpa_commit() { asm volatile("cp.async.commit_group;\n"); }
__device__ __forceinline__ void cpa_wait0() { asm volatile("cp.async.wait_group 0;\n"); }
__device__ __forceinline__ void cpa_wait1() { asm volatile("cp.async.wait_group 1;\n"); }
__device__ __forceinline__ void cpa_wait2() { asm volatile("cp.async.wait_group 2;\n"); }

// ---- K0: scalars, m_k, U2/U3 tables, base ----------------------------------
__global__ void k_prep(const float* wb, const float* fb, const float* ig,
                       const float* bg, const float* cg, const float* bt,
                       const float* rr, const float* ri, const float* sig,
                       const float* Vmr, const float* Vmi) {
    int e = threadIdx.x;  // 1024
    float gc = sigmoidf_(cg[0]);
    if (e < K_) {
        float scale = (e == 0 ? 1.0f : 2.0f) / (float)W_;
        g_m[e] = scale * sig[e] * (wb[e] + fb[e]);
    }
    if (e == 0) g_sout = sigmoidf_(ig[0]) * bg[0];
    float sr = 0.f, si = 0.f;
    #pragma unroll
    for (int k = 0; k < NRB_; k++) {
        float tr = sigmoidf_(bt[k]);
        sr += tr * rr[k * D_ + e];
        si += tr * ri[k * D_ + e];
    }
    g_base[e] = ALPHA_ * (sr * Vmr[e] + si * Vmi[e]);
    float c2 = (1.0f - ALPHA_) * (1.0f - gc);
    float c3 = (1.0f - ALPHA_) * gc;
    #pragma unroll
    for (int k = 0; k < K_; k++) {
        float U = sr * rr[k * D_ + e] + si * ri[k * D_ + e];
        g_U2[k * D_ + e] = c2 * U;
        g_U3[k * D_ + e] = c3 * U;
    }
}

// ---- K0b: elementwise fp16 casts --------------------------------------------
__global__ void k_cast(const float* __restrict__ Wc, const float* __restrict__ Rw) {
    size_t i = (size_t)blockIdx.x * blockDim.x + threadIdx.x;  // float4 granule
    float4 w = ((const float4*)Wc)[i];
    float4 r = ((const float4*)Rw)[i];
    __half2* wd = (__half2*)&g_Wch[i * 4];
    __half2* rd = (__half2*)&g_Rwh[i * 4];
    wd[0] = __floats2half2_rn(w.x, w.y);
    wd[1] = __floats2half2_rn(w.z, w.w);
    rd[0] = __floats2half2_rn(r.x, r.y);
    rd[1] = __floats2half2_rn(r.z, r.w);
}

// ---- K1: tf32 tensor cheby, 3-buffer 16-row pipeline (2 CTAs/SM) -------------
// Proven ordering: load(c+2) -> wait2 -> sync -> compute(c) -> sync.
#define CH_DT 256
#define CH_LD 264
#define CH_NS 3
__global__ __launch_bounds__(256) void k_cheby(const float* __restrict__ x,
                                               const float* __restrict__ C) {
    extern __shared__ float sh[];
    float* sC = sh;                      // [32][CH_LD]
    float* xs = sh + 32 * CH_LD;         // CH_NS x [16][CH_LD]
    __shared__ float sm[K_];
    int tid = threadIdx.x;
    int wid = tid >> 5;
    int b   = blockIdx.y;
    int d0  = blockIdx.x * CH_DT;
    const float* xb = x + (size_t)b * W_ * D_ + d0;

    auto load_chunk = [&](int c) {
        float* dst = xs + (c % CH_NS) * 16 * CH_LD;
        const float* src = xb + (size_t)c * 16 * D_;
        #pragma unroll
        for (int i = 0; i < 4; i++) {
            int idx = i * 256 + tid;          // 0..1023 16B segs
            int r = idx >> 6, seg = idx & 63; // row 0..15
            cpa16(dst + r * CH_LD + seg * 4, src + (size_t)r * D_ + seg * 4);
        }
        cpa_commit();
    };

    load_chunk(0);
    load_chunk(1);

    for (int i = tid; i < K_ * W_; i += 256)
        sC[(i >> 8) * CH_LD + (i & 255)] = C[i];
    if (tid < K_) sm[tid] = g_m[tid];

    wmma::fragment<wmma::accumulator, 16, 16, 8, float> acc[2][2];
    #pragma unroll
    for (int i = 0; i < 2; i++)
        #pragma unroll
        for (int j = 0; j < 2; j++) wmma::fill_fragment(acc[i][j], 0.0f);

    for (int c = 0; c < 16; c++) {
        if (c + 2 < 16) load_chunk(c + 2);   // writes buffer (c-1)%3: done last iter
        else cpa_commit();                   // keep group count uniform
        cpa_wait2();                         // <=2 pending (c+1, c+2) -> chunk c done
        __syncthreads();
        float* xc = xs + (c % CH_NS) * 16 * CH_LD;
        #pragma unroll
        for (int ks = 0; ks < 2; ks++) {
            wmma::fragment<wmma::matrix_a, 16, 16, 8, wmma::precision::tf32, wmma::row_major> af[2];
            wmma::fragment<wmma::matrix_b, 16, 16, 8, wmma::precision::tf32, wmma::row_major> bf[2];
            #pragma unroll
            for (int i = 0; i < 2; i++)
                wmma::load_matrix_sync(af[i], &sC[(i * 16) * CH_LD + c * 16 + ks * 8], CH_LD);
            #pragma unroll
            for (int j = 0; j < 2; j++)
                wmma::load_matrix_sync(bf[j], &xc[(ks * 8) * CH_LD + wid * 32 + j * 16], CH_LD);
            #pragma unroll
            for (int i = 0; i < 2; i++)
                #pragma unroll
                for (int j = 0; j < 2; j++)
                    wmma::mma_sync(acc[i][j], af[i], bf[j], acc[i][j]);
        }
        __syncthreads();
    }

    float* sA = sh;
    #pragma unroll
    for (int i = 0; i < 2; i++)
        #pragma unroll
        for (int j = 0; j < 2; j++)
            wmma::store_matrix_sync(&sA[(i * 16) * CH_LD + wid * 32 + j * 16],
                                    acc[i][j], CH_LD, wmma::mem_row_major);
    __syncthreads();
    int dg = d0 + tid;
    float rA = 0.f;
    size_t abase = ((size_t)b * K_) * D_ + dg;
    #pragma unroll
    for (int k = 0; k < K_; k++) {
        float v = sm[k] * sA[k * CH_LD + tid];
        rA += g_U2[k * D_ + dg] * v;
        g_Ah[abase + (size_t)k * D_] = __float2half(v);
    }
    g_rA[(size_t)b * D_ + dg] = rA;
}

// ---- K2: G = Ah @ Wch^T (fp16 accum), R6/R8 proven config, fused U3 epi ------
#define GM 128
#define GN 128
#define GK 64
#define ALD 72
#define BLD 72
#define SLD 136
__global__ __launch_bounds__(256) void k_gemm() {
    extern __shared__ char shg[];
    __half* As = (__half*)shg;                                   // 2 x [128][ALD]
    __half* Bs = (__half*)(shg + 2 * GM * ALD * sizeof(__half)); // 2 x [128][BLD]
    __half* Sgh = (__half*)shg;                                   // epi [128][SLD]
    int tid = threadIdx.x;
    int wid = tid >> 5;
    int wm = wid >> 1, wn = wid & 1;  // 4x2 warps, warp tile 32(m) x 64(n)
    size_t m0 = (size_t)blockIdx.y * GM;
    size_t n0 = (size_t)blockIdx.x * GN;

    wmma::fragment<wmma::accumulator, 16, 16, 16, __half> acc[2][4];
    #pragma unroll
    for (int i = 0; i < 2; i++)
        #pragma unroll
        for (int j = 0; j < 4; j++) wmma::fill_fragment(acc[i][j], __float2half(0.0f));

    auto load_stage = [&](int it) {
        int s = it & 1;
        const __half* Ag = &g_Ah [m0 * D_ + (size_t)it * GK];
        const __half* Bg = &g_Wch[n0 * D_ + (size_t)it * GK];
        __half* Ad = &As[s * GM * ALD];
        __half* Bd = &Bs[s * GN * BLD];
        #pragma unroll
        for (int i = 0; i < 4; i++) {
            int idx = i * 256 + tid;
            int r = idx >> 3, seg = idx & 7;
            cpa16(Ad + r * ALD + seg * 8, Ag + (size_t)r * D_ + seg * 8);
        }
        #pragma unroll
        for (int i = 0; i < 4; i++) {
            int idx = i * 256 + tid;
            int r = idx >> 3, seg = idx & 7;
            cpa16(Bd + r * BLD + seg * 8, Bg + (size_t)r * D_ + seg * 8);
        }
        cpa_commit();
    };

    load_stage(0);

    for (int it = 0; it < D_ / GK; it++) {
        if (it < D_ / GK - 1) {
            load_stage(it + 1);
            cpa_wait1();
        } else {
            cpa_wait0();
        }
        __syncthreads();
        int s = it & 1;
        const __half* Ab = &As[s * GM * ALD];
        const __half* Bb = &Bs[s * GN * BLD];
        #pragma unroll
        for (int ks = 0; ks < 4; ks++) {
            wmma::fragment<wmma::matrix_a, 16, 16, 16, __half, wmma::row_major> af[2];
            wmma::fragment<wmma::matrix_b, 16, 16, 16, __half, wmma::col_major> bf[4];
            #pragma unroll
            for (int i = 0; i < 2; i++)
                wmma::load_matrix_sync(af[i], &Ab[(wm * 32 + i * 16) * ALD + ks * 16], ALD);
            #pragma unroll
            for (int j = 0; j < 4; j++)
                wmma::load_matrix_sync(bf[j], &Bb[(wn * 64 + j * 16) * BLD + ks * 16], BLD);
            #pragma unroll
            for (int i = 0; i < 2; i++)
                #pragma unroll
                for (int j = 0; j < 4; j++)
                    wmma::mma_sync(acc[i][j], af[i], bf[j], acc[i][j]);
        }
        __syncthreads();
    }

    #pragma unroll
    for (int i = 0; i < 2; i++)
        #pragma unroll
        for (int j = 0; j < 4; j++)
            wmma::store_matrix_sync(&Sgh[(wm * 32 + i * 16) * SLD + wn * 64 + j * 16],
                                    acc[i][j], SLD, wmma::mem_row_major);
    __syncthreads();
    int e  = tid & 127;
    int bh = tid >> 7;
    int eg = (int)n0 + e;
    #pragma unroll
    for (int ob = 0; ob < 2; ob++) {
        int b4 = ob * 2 + bh;
        float sacc = 0.f;
        #pragma unroll
        for (int k = 0; k < K_; k++)
            sacc += g_U3[k * D_ + eg] * __half2float(Sgh[(b4 * 32 + k) * SLD + e]);
        int bg = (int)(m0 >> 5) + b4;
        g_retrh[(size_t)bg * D_ + eg] =
            __float2half(g_base[eg] + g_rA[(size_t)bg * D_ + eg] + sacc);
    }
}

// ---- K4: retr2 = retrh @ Rwh^T, GM=64 tiles (32 blocks), R8 proven -----------
#define G2M 64
#define G2N 128
#define G2K 64
#define A2LD 72
#define B2LD 72
__global__ __launch_bounds__(256) void k_gemm2() {
    extern __shared__ char shg[];
    __half* As = (__half*)shg;                                     // 2 x [64][A2LD]
    __half* Bs = (__half*)(shg + 2 * G2M * A2LD * sizeof(__half)); // 2 x [128][B2LD]
    int tid = threadIdx.x;
    int wid = tid >> 5;
    int wm = wid >> 1, wn = wid & 1;  // 4(m) x 2(n), warp tile 16 x 64
    size_t m0 = (size_t)blockIdx.y * G2M;
    size_t n0 = (size_t)blockIdx.x * G2N;

    wmma::fragment<wmma::accumulator, 16, 16, 16, float> acc[4];
    #pragma unroll
    for (int j = 0; j < 4; j++) wmma::fill_fragment(acc[j], 0.0f);

    auto load_stage = [&](int it) {
        int s = it & 1;
        const __half* Ag = &g_retrh[m0 * D_ + (size_t)it * G2K];
        const __half* Bg = &g_Rwh  [n0 * D_ + (size_t)it * G2K];
        __half* Ad = &As[s * G2M * A2LD];
        __half* Bd = &Bs[s * G2N * B2LD];
        #pragma unroll
        for (int i = 0; i < 2; i++) {
            int idx = i * 256 + tid;          // 0..511
            int r = idx >> 3, seg = idx & 7;  // row 0..63
            cpa16(Ad + r * A2LD + seg * 8, Ag + (size_t)r * D_ + seg * 8);
        }
        #pragma unroll
        for (int i = 0; i < 4; i++) {
            int idx = i * 256 + tid;
            int r = idx >> 3, seg = idx & 7;
            cpa16(Bd + r * B2LD + seg * 8, Bg + (size_t)r * D_ + seg * 8);
        }
        cpa_commit();
    };

    load_stage(0);

    for (int it = 0; it < D_ / G2K; it++) {
        if (it < D_ / G2K - 1) {
            load_stage(it + 1);
            cpa_wait1();
        } else {
            cpa_wait0();
        }
        __syncthreads();
        int s = it & 1;
        const __half* Ab = &As[s * G2M * A2LD];
        const __half* Bb = &Bs[s * G2N * B2LD];
        #pragma unroll
        for (int ks = 0; ks < 4; ks++) {
            wmma::fragment<wmma::matrix_a, 16, 16, 16, __half, wmma::row_major> af;
            wmma::fragment<wmma::matrix_b, 16, 16, 16, __half, wmma::col_major> bf[4];
            wmma::load_matrix_sync(af, &Ab[(wm * 16) * A2LD + ks * 16], A2LD);
            #pragma unroll
            for (int j = 0; j < 4; j++)
                wmma::load_matrix_sync(bf[j], &Bb[(wn * 64 + j * 16) * B2LD + ks * 16], B2LD);
            #pragma unroll
            for (int j = 0; j < 4; j++)
                wmma::mma_sync(acc[j], af, bf[j], acc[j]);
        }
        __syncthreads();
    }

    #pragma unroll
    for (int j = 0; j < 4; j++)
        wmma::store_matrix_sync(
            &g_retr2[(m0 + wm * 16) * D_ + n0 + wn * 64 + j * 16],
            acc[j], D_, wmma::mem_row_major);
}

// ---- K5: out = x + s * retr2; each thread does rows (b,w) and (b,w+128) ------
__global__ void k_out(const float* __restrict__ x, float* __restrict__ out) {
    size_t t = (size_t)blockIdx.x * blockDim.x + threadIdx.x;  // 0 .. B*W/2*D/4
    int d4 = (int)(t & (D_ / 4 - 1));
    size_t rest = t >> 8;            // / (D_/4)
    int w = (int)(rest & (W_ / 2 - 1));
    int b = (int)(rest >> 7);        // / (W_/2)
    float s = g_sout;
    float4 rv = __ldg(&((const float4*)g_retr2)[(size_t)b * (D_ / 4) + d4]);
    size_t i4a = ((size_t)(b * W_ + w) * (D_ / 4)) + d4;
    size_t i4b = i4a + (size_t)(W_ / 2) * (D_ / 4);
    float4 xa = __ldcs(&((const float4*)x)[i4a]);
    float4 xb = __ldcs(&((const float4*)x)[i4b]);
    float4 oa, ob;
    oa.x = xa.x + s * rv.x; oa.y = xa.y + s * rv.y;
    oa.z = xa.z + s * rv.z; oa.w = xa.w + s * rv.w;
    ob.x = xb.x + s * rv.x; ob.y = xb.y + s * rv.y;
    ob.z = xb.z + s * rv.z; ob.w = xb.w + s * rv.w;
    __stcs(&((float4*)out)[i4a], oa);
    __stcs(&((float4*)out)[i4b], ob);
}

extern "C" void kernel_launch(void* const* d_in, const int* in_sizes, int n_in,
                              void* d_out, int out_size) {
    const float* x   = (const float*)d_in[0];
    const float* wb  = (const float*)d_in[1];
    const float* fb  = (const float*)d_in[2];
    const float* ig  = (const float*)d_in[3];
    const float* bg  = (const float*)d_in[4];
    const float* cg  = (const float*)d_in[5];
    const float* bt  = (const float*)d_in[6];
    const float* Wc  = (const float*)d_in[7];
    const float* Rw  = (const float*)d_in[8];
    const float* rr  = (const float*)d_in[9];
    const float* ri  = (const float*)d_in[10];
    const float* Vmr = (const float*)d_in[11];
    const float* Vmi = (const float*)d_in[12];
    const float* C   = (const float*)d_in[13];
    const float* sig = (const float*)d_in[14];
    float* out = (float*)d_out;

    const int cheby_smem = (32 + CH_NS * 16) * CH_LD * 4;                        // 84480
    const int gemm_smem  = 2 * (GM * ALD + GN * BLD) * (int)sizeof(__half);      // 73728
    const int gemm2_smem = 2 * (G2M * A2LD + G2N * B2LD) * (int)sizeof(__half);  // 55296

    static cudaStream_t s_side = nullptr;
    static cudaEvent_t ev_fork = nullptr, ev_join = nullptr;
    static bool init_done = false;
    if (!init_done) {
        cudaFuncSetAttribute(k_cheby, cudaFuncAttributeMaxDynamicSharedMemorySize,
                             cheby_smem);
        cudaFuncSetAttribute(k_gemm, cudaFuncAttributeMaxDynamicSharedMemorySize,
                             gemm_smem);
        cudaFuncSetAttribute(k_gemm2, cudaFuncAttributeMaxDynamicSharedMemorySize,
                             gemm2_smem);
        cudaStreamCreateWithFlags(&s_side, cudaStreamNonBlocking);
        cudaEventCreateWithFlags(&ev_fork, cudaEventDisableTiming);
        cudaEventCreateWithFlags(&ev_join, cudaEventDisableTiming);
        init_done = true;
    }

    // fork: k_cast is independent of prep/cheby
    cudaEventRecord(ev_fork, 0);
    cudaStreamWaitEvent(s_side, ev_fork, 0);
    k_cast<<<(D_ * D_ / 4) / 256, 256, 0, s_side>>>(Wc, Rw);
    cudaEventRecord(ev_join, s_side);

    k_prep<<<1, 1024>>>(wb, fb, ig, bg, cg, bt, rr, ri, sig, Vmr, Vmi);
    k_cheby<<<dim3(D_ / CH_DT, B_), 256, cheby_smem>>>(x, C);

    // join before the GEMMs (they consume g_Wch / g_Rwh)
    cudaStreamWaitEvent(0, ev_join, 0);
    k_gemm<<<dim3(D_ / GN, (B_ * K_) / GM), 256, gemm_smem>>>();
    k_gemm2<<<dim3(D_ / G2N, B_ / G2M), 256, gemm2_smem>>>();
    k_out<<<(B_ * W_ * D_ / 8) / 256, 256>>>(x, out);
}

// round 15
// speedup vs baseline: 1.0498x; 1.0094x over previous
#include <cuda_runtime.h>
#include <cuda_fp16.h>
#include <mma.h>
#include <cstdint>
using namespace nvcuda;

#define B_  256
#define W_  256
#define D_  1024
#define K_  32
#define NRB_ 8
#define ALPHA_ 0.9f

// ---- scratch ----
__device__ __half  g_Ah  [B_*K_*D_];   // 16 MB  fp16 of m_k*(C@x)
__device__ __half  g_Wch [D_*D_];      //  2 MB  compress_W fp16 (as-is, [e,d])
__device__ __half  g_Rwh [D_*D_];      //  2 MB  retrieve_W fp16 (as-is, [e,d])
__device__ float   g_rA  [B_*D_];      //  1 MB  sum_k U2*A
__device__ __half  g_retrh[B_*D_];     // fp16 retr
__device__ float   g_retr2[B_*D_];
__device__ float   g_m[K_];
__device__ float   g_U2[K_*D_];
__device__ float   g_U3[K_*D_];
__device__ float   g_base[D_];
__device__ float   g_sout;

__device__ __forceinline__ float sigmoidf_(float v) { return 1.0f / (1.0f + expf(-v)); }

__device__ __forceinline__ void cpa16(void* smem, const void* gmem) {
    unsigned sa = (unsigned)__cvta_generic_to_shared(smem);
    asm volatile("cp.async.cg.shared.global [%0], [%1], 16;\n" :: "r"(sa), "l"(gmem));
}
__device__ __forceinline__ void cpa_commit() { asm volatile("cp.async.commit_group;\n"); }
__device__ __forceinline__ void cpa_wait0() { asm volatile("cp.async.wait_group 0;\n"); }
__device__ __forceinline__ void cpa_wait1() { asm volatile("cp.async.wait_group 1;\n"); }
__device__ __forceinline__ void cpa_wait2() { asm volatile("cp.async.wait_group 2;\n"); }

// ---- K0: scalars, m_k, U2/U3 tables, base ----------------------------------
__global__ void k_prep(const float* wb, const float* fb, const float* ig,
                       const float* bg, const float* cg, const float* bt,
                       const float* rr, const float* ri, const float* sig,
                       const float* Vmr, const float* Vmi) {
    int e = threadIdx.x;  // 1024
    float gc = sigmoidf_(cg[0]);
    if (e < K_) {
        float scale = (e == 0 ? 1.0f : 2.0f) / (float)W_;
        g_m[e] = scale * sig[e] * (wb[e] + fb[e]);
    }
    if (e == 0) g_sout = sigmoidf_(ig[0]) * bg[0];
    float sr = 0.f, si = 0.f;
    #pragma unroll
    for (int k = 0; k < NRB_; k++) {
        float tr = sigmoidf_(bt[k]);
        sr += tr * rr[k * D_ + e];
        si += tr * ri[k * D_ + e];
    }
    g_base[e] = ALPHA_ * (sr * Vmr[e] + si * Vmi[e]);
    float c2 = (1.0f - ALPHA_) * (1.0f - gc);
    float c3 = (1.0f - ALPHA_) * gc;
    #pragma unroll
    for (int k = 0; k < K_; k++) {
        float U = sr * rr[k * D_ + e] + si * ri[k * D_ + e];
        g_U2[k * D_ + e] = c2 * U;
        g_U3[k * D_ + e] = c3 * U;
    }
}

// ---- K0b: elementwise fp16 casts --------------------------------------------
__global__ void k_cast(const float* __restrict__ Wc, const float* __restrict__ Rw) {
    size_t i = (size_t)blockIdx.x * blockDim.x + threadIdx.x;  // float4 granule
    float4 w = ((const float4*)Wc)[i];
    float4 r = ((const float4*)Rw)[i];
    __half2* wd = (__half2*)&g_Wch[i * 4];
    __half2* rd = (__half2*)&g_Rwh[i * 4];
    wd[0] = __floats2half2_rn(w.x, w.y);
    wd[1] = __floats2half2_rn(w.z, w.w);
    rd[0] = __floats2half2_rn(r.x, r.y);
    rd[1] = __floats2half2_rn(r.z, r.w);
}

// ---- K1: tf32 tensor cheby, PER-WARP private x rings, barrier-free mainloop --
#define CH_DT 256
#define CH_LD 264
#define CH_WLD 36    // per-warp buffer row stride (floats): 36 mod 32 = 4 rotation
#define CH_WNS 3     // per-warp ring depth
#define CH_WBUF (CH_WNS * 16 * CH_WLD)   // floats per warp
__global__ __launch_bounds__(256) void k_cheby(const float* __restrict__ x,
                                               const float* __restrict__ C) {
    extern __shared__ float sh[];
    float* sC = sh;                          // [32][CH_LD] (shared across warps)
    __shared__ float sm[K_];
    int tid  = threadIdx.x;
    int wid  = tid >> 5;
    int lane = tid & 31;
    int b    = blockIdx.y;
    int d0   = blockIdx.x * CH_DT;
    float* wbuf = sh + 32 * CH_LD + wid * CH_WBUF;   // this warp's private ring
    // warp's 32-col slice of x
    const float* xw = x + (size_t)b * W_ * D_ + d0 + wid * 32;

    // warp-local chunk load: 16 rows x 32 cols = 128 x 16B segs, 4 per lane
    auto load_chunk = [&](int c) {
        float* dst = wbuf + (c % CH_WNS) * 16 * CH_WLD;
        const float* src = xw + (size_t)c * 16 * D_;
        #pragma unroll
        for (int i = 0; i < 4; i++) {
            int idx = i * 32 + lane;          // 0..127
            int r = idx >> 3, seg = idx & 7;  // row 0..15, seg 0..7
            cpa16(dst + r * CH_WLD + seg * 4, src + (size_t)r * D_ + seg * 4);
        }
        cpa_commit();
    };

    load_chunk(0);
    load_chunk(1);

    for (int i = tid; i < K_ * W_; i += 256)
        sC[(i >> 8) * CH_LD + (i & 255)] = C[i];
    if (tid < K_) sm[tid] = g_m[tid];
    __syncthreads();   // sC visible to all warps; after this, NO in-loop barriers

    wmma::fragment<wmma::accumulator, 16, 16, 8, float> acc[2][2];
    #pragma unroll
    for (int i = 0; i < 2; i++)
        #pragma unroll
        for (int j = 0; j < 2; j++) wmma::fill_fragment(acc[i][j], 0.0f);

    for (int c = 0; c < 16; c++) {
        if (c + 2 < 16) load_chunk(c + 2);   // private buffer (c-1)%3: this warp done
        else cpa_commit();                   // uniform per-thread group count
        cpa_wait2();                         // chunk c landed (per-thread semantics)
        float* xc = wbuf + (c % CH_WNS) * 16 * CH_WLD;
        #pragma unroll
        for (int ks = 0; ks < 2; ks++) {
            wmma::fragment<wmma::matrix_a, 16, 16, 8, wmma::precision::tf32, wmma::row_major> af[2];
            wmma::fragment<wmma::matrix_b, 16, 16, 8, wmma::precision::tf32, wmma::row_major> bf[2];
            #pragma unroll
            for (int i = 0; i < 2; i++)
                wmma::load_matrix_sync(af[i], &sC[(i * 16) * CH_LD + c * 16 + ks * 8], CH_LD);
            #pragma unroll
            for (int j = 0; j < 2; j++)
                wmma::load_matrix_sync(bf[j], &xc[(ks * 8) * CH_WLD + j * 16], CH_WLD);
            #pragma unroll
            for (int i = 0; i < 2; i++)
                #pragma unroll
                for (int j = 0; j < 2; j++)
                    wmma::mma_sync(acc[i][j], af[i], bf[j], acc[i][j]);
        }
    }
    __syncthreads();   // all warps done reading sC before epilogue aliases it

    float* sA = sh;    // [32][CH_LD] staging (overwrites sC)
    #pragma unroll
    for (int i = 0; i < 2; i++)
        #pragma unroll
        for (int j = 0; j < 2; j++)
            wmma::store_matrix_sync(&sA[(i * 16) * CH_LD + wid * 32 + j * 16],
                                    acc[i][j], CH_LD, wmma::mem_row_major);
    __syncthreads();
    int dg = d0 + tid;
    float rA = 0.f;
    size_t abase = ((size_t)b * K_) * D_ + dg;
    #pragma unroll
    for (int k = 0; k < K_; k++) {
        float v = sm[k] * sA[k * CH_LD + tid];
        rA += g_U2[k * D_ + dg] * v;
        g_Ah[abase + (size_t)k * D_] = __float2half(v);
    }
    g_rA[(size_t)b * D_ + dg] = rA;
}

// ---- K2: G = Ah @ Wch^T (fp16 accum), R6/R8 proven config, fused U3 epi ------
#define GM 128
#define GN 128
#define GK 64
#define ALD 72
#define BLD 72
#define SLD 136
__global__ __launch_bounds__(256) void k_gemm() {
    extern __shared__ char shg[];
    __half* As = (__half*)shg;                                   // 2 x [128][ALD]
    __half* Bs = (__half*)(shg + 2 * GM * ALD * sizeof(__half)); // 2 x [128][BLD]
    __half* Sgh = (__half*)shg;                                   // epi [128][SLD]
    int tid = threadIdx.x;
    int wid = tid >> 5;
    int wm = wid >> 1, wn = wid & 1;  // 4x2 warps, warp tile 32(m) x 64(n)
    size_t m0 = (size_t)blockIdx.y * GM;
    size_t n0 = (size_t)blockIdx.x * GN;

    wmma::fragment<wmma::accumulator, 16, 16, 16, __half> acc[2][4];
    #pragma unroll
    for (int i = 0; i < 2; i++)
        #pragma unroll
        for (int j = 0; j < 4; j++) wmma::fill_fragment(acc[i][j], __float2half(0.0f));

    auto load_stage = [&](int it) {
        int s = it & 1;
        const __half* Ag = &g_Ah [m0 * D_ + (size_t)it * GK];
        const __half* Bg = &g_Wch[n0 * D_ + (size_t)it * GK];
        __half* Ad = &As[s * GM * ALD];
        __half* Bd = &Bs[s * GN * BLD];
        #pragma unroll
        for (int i = 0; i < 4; i++) {
            int idx = i * 256 + tid;
            int r = idx >> 3, seg = idx & 7;
            cpa16(Ad + r * ALD + seg * 8, Ag + (size_t)r * D_ + seg * 8);
        }
        #pragma unroll
        for (int i = 0; i < 4; i++) {
            int idx = i * 256 + tid;
            int r = idx >> 3, seg = idx & 7;
            cpa16(Bd + r * BLD + seg * 8, Bg + (size_t)r * D_ + seg * 8);
        }
        cpa_commit();
    };

    load_stage(0);

    for (int it = 0; it < D_ / GK; it++) {
        if (it < D_ / GK - 1) {
            load_stage(it + 1);
            cpa_wait1();
        } else {
            cpa_wait0();
        }
        __syncthreads();
        int s = it & 1;
        const __half* Ab = &As[s * GM * ALD];
        const __half* Bb = &Bs[s * GN * BLD];
        #pragma unroll
        for (int ks = 0; ks < 4; ks++) {
            wmma::fragment<wmma::matrix_a, 16, 16, 16, __half, wmma::row_major> af[2];
            wmma::fragment<wmma::matrix_b, 16, 16, 16, __half, wmma::col_major> bf[4];
            #pragma unroll
            for (int i = 0; i < 2; i++)
                wmma::load_matrix_sync(af[i], &Ab[(wm * 32 + i * 16) * ALD + ks * 16], ALD);
            #pragma unroll
            for (int j = 0; j < 4; j++)
                wmma::load_matrix_sync(bf[j], &Bb[(wn * 64 + j * 16) * BLD + ks * 16], BLD);
            #pragma unroll
            for (int i = 0; i < 2; i++)
                #pragma unroll
                for (int j = 0; j < 4; j++)
                    wmma::mma_sync(acc[i][j], af[i], bf[j], acc[i][j]);
        }
        __syncthreads();
    }

    #pragma unroll
    for (int i = 0; i < 2; i++)
        #pragma unroll
        for (int j = 0; j < 4; j++)
            wmma::store_matrix_sync(&Sgh[(wm * 32 + i * 16) * SLD + wn * 64 + j * 16],
                                    acc[i][j], SLD, wmma::mem_row_major);
    __syncthreads();
    int e  = tid & 127;
    int bh = tid >> 7;
    int eg = (int)n0 + e;
    #pragma unroll
    for (int ob = 0; ob < 2; ob++) {
        int b4 = ob * 2 + bh;
        float sacc = 0.f;
        #pragma unroll
        for (int k = 0; k < K_; k++)
            sacc += g_U3[k * D_ + eg] * __half2float(Sgh[(b4 * 32 + k) * SLD + e]);
        int bg = (int)(m0 >> 5) + b4;
        g_retrh[(size_t)bg * D_ + eg] =
            __float2half(g_base[eg] + g_rA[(size_t)bg * D_ + eg] + sacc);
    }
}

// ---- K4: retr2 = retrh @ Rwh^T, GM=64 tiles (32 blocks), R8 proven -----------
#define G2M 64
#define G2N 128
#define G2K 64
#define A2LD 72
#define B2LD 72
__global__ __launch_bounds__(256) void k_gemm2() {
    extern __shared__ char shg[];
    __half* As = (__half*)shg;                                     // 2 x [64][A2LD]
    __half* Bs = (__half*)(shg + 2 * G2M * A2LD * sizeof(__half)); // 2 x [128][B2LD]
    int tid = threadIdx.x;
    int wid = tid >> 5;
    int wm = wid >> 1, wn = wid & 1;  // 4(m) x 2(n), warp tile 16 x 64
    size_t m0 = (size_t)blockIdx.y * G2M;
    size_t n0 = (size_t)blockIdx.x * G2N;

    wmma::fragment<wmma::accumulator, 16, 16, 16, float> acc[4];
    #pragma unroll
    for (int j = 0; j < 4; j++) wmma::fill_fragment(acc[j], 0.0f);

    auto load_stage = [&](int it) {
        int s = it & 1;
        const __half* Ag = &g_retrh[m0 * D_ + (size_t)it * G2K];
        const __half* Bg = &g_Rwh  [n0 * D_ + (size_t)it * G2K];
        __half* Ad = &As[s * G2M * A2LD];
        __half* Bd = &Bs[s * G2N * B2LD];
        #pragma unroll
        for (int i = 0; i < 2; i++) {
            int idx = i * 256 + tid;          // 0..511
            int r = idx >> 3, seg = idx & 7;  // row 0..63
            cpa16(Ad + r * A2LD + seg * 8, Ag + (size_t)r * D_ + seg * 8);
        }
        #pragma unroll
        for (int i = 0; i < 4; i++) {
            int idx = i * 256 + tid;
            int r = idx >> 3, seg = idx & 7;
            cpa16(Bd + r * B2LD + seg * 8, Bg + (size_t)r * D_ + seg * 8);
        }
        cpa_commit();
    };

    load_stage(0);

    for (int it = 0; it < D_ / G2K; it++) {
        if (it < D_ / G2K - 1) {
            load_stage(it + 1);
            cpa_wait1();
        } else {
            cpa_wait0();
        }
        __syncthreads();
        int s = it & 1;
        const __half* Ab = &As[s * G2M * A2LD];
        const __half* Bb = &Bs[s * G2N * B2LD];
        #pragma unroll
        for (int ks = 0; ks < 4; ks++) {
            wmma::fragment<wmma::matrix_a, 16, 16, 16, __half, wmma::row_major> af;
            wmma::fragment<wmma::matrix_b, 16, 16, 16, __half, wmma::col_major> bf[4];
            wmma::load_matrix_sync(af, &Ab[(wm * 16) * A2LD + ks * 16], A2LD);
            #pragma unroll
            for (int j = 0; j < 4; j++)
                wmma::load_matrix_sync(bf[j], &Bb[(wn * 64 + j * 16) * B2LD + ks * 16], B2LD);
            #pragma unroll
            for (int j = 0; j < 4; j++)
                wmma::mma_sync(acc[j], af, bf[j], acc[j]);
        }
        __syncthreads();
    }

    #pragma unroll
    for (int j = 0; j < 4; j++)
        wmma::store_matrix_sync(
            &g_retr2[(m0 + wm * 16) * D_ + n0 + wn * 64 + j * 16],
            acc[j], D_, wmma::mem_row_major);
}

// ---- K5: out = x + s * retr2; each thread does rows (b,w) and (b,w+128) ------
__global__ void k_out(const float* __restrict__ x, float* __restrict__ out) {
    size_t t = (size_t)blockIdx.x * blockDim.x + threadIdx.x;  // 0 .. B*W/2*D/4
    int d4 = (int)(t & (D_ / 4 - 1));
    size_t rest = t >> 8;            // / (D_/4)
    int w = (int)(rest & (W_ / 2 - 1));
    int b = (int)(rest >> 7);        // / (W_/2)
    float s = g_sout;
    float4 rv = __ldg(&((const float4*)g_retr2)[(size_t)b * (D_ / 4) + d4]);
    size_t i4a = ((size_t)(b * W_ + w) * (D_ / 4)) + d4;
    size_t i4b = i4a + (size_t)(W_ / 2) * (D_ / 4);
    float4 xa = __ldcs(&((const float4*)x)[i4a]);
    float4 xb = __ldcs(&((const float4*)x)[i4b]);
    float4 oa, ob;
    oa.x = xa.x + s * rv.x; oa.y = xa.y + s * rv.y;
    oa.z = xa.z + s * rv.z; oa.w = xa.w + s * rv.w;
    ob.x = xb.x + s * rv.x; ob.y = xb.y + s * rv.y;
    ob.z = xb.z + s * rv.z; ob.w = xb.w + s * rv.w;
    __stcs(&((float4*)out)[i4a], oa);
    __stcs(&((float4*)out)[i4b], ob);
}

extern "C" void kernel_launch(void* const* d_in, const int* in_sizes, int n_in,
                              void* d_out, int out_size) {
    const float* x   = (const float*)d_in[0];
    const float* wb  = (const float*)d_in[1];
    const float* fb  = (const float*)d_in[2];
    const float* ig  = (const float*)d_in[3];
    const float* bg  = (const float*)d_in[4];
    const float* cg  = (const float*)d_in[5];
    const float* bt  = (const float*)d_in[6];
    const float* Wc  = (const float*)d_in[7];
    const float* Rw  = (const float*)d_in[8];
    const float* rr  = (const float*)d_in[9];
    const float* ri  = (const float*)d_in[10];
    const float* Vmr = (const float*)d_in[11];
    const float* Vmi = (const float*)d_in[12];
    const float* C   = (const float*)d_in[13];
    const float* sig = (const float*)d_in[14];
    float* out = (float*)d_out;

    const int cheby_smem = (32 * CH_LD + 8 * CH_WBUF) * 4;                       // 89088
    const int gemm_smem  = 2 * (GM * ALD + GN * BLD) * (int)sizeof(__half);      // 73728
    const int gemm2_smem = 2 * (G2M * A2LD + G2N * B2LD) * (int)sizeof(__half);  // 55296

    static cudaStream_t s_side = nullptr;
    static cudaEvent_t ev_fork = nullptr, ev_join = nullptr;
    static bool init_done = false;
    if (!init_done) {
        cudaFuncSetAttribute(k_cheby, cudaFuncAttributeMaxDynamicSharedMemorySize,
                             cheby_smem);
        cudaFuncSetAttribute(k_gemm, cudaFuncAttributeMaxDynamicSharedMemorySize,
                             gemm_smem);
        cudaFuncSetAttribute(k_gemm2, cudaFuncAttributeMaxDynamicSharedMemorySize,
                             gemm2_smem);
        cudaStreamCreateWithFlags(&s_side, cudaStreamNonBlocking);
        cudaEventCreateWithFlags(&ev_fork, cudaEventDisableTiming);
        cudaEventCreateWithFlags(&ev_join, cudaEventDisableTiming);
        init_done = true;
    }

    // fork: k_cast is independent of prep/cheby
    cudaEventRecord(ev_fork, 0);
    cudaStreamWaitEvent(s_side, ev_fork, 0);
    k_cast<<<(D_ * D_ / 4) / 256, 256, 0, s_side>>>(Wc, Rw);
    cudaEventRecord(ev_join, s_side);

    k_prep<<<1, 1024>>>(wb, fb, ig, bg, cg, bt, rr, ri, sig, Vmr, Vmi);
    k_cheby<<<dim3(D_ / CH_DT, B_), 256, cheby_smem>>>(x, C);

    // join before the GEMMs (they consume g_Wch / g_Rwh)
    cudaStreamWaitEvent(0, ev_join, 0);
    k_gemm<<<dim3(D_ / GN, (B_ * K_) / GM), 256, gemm_smem>>>();
    k_gemm2<<<dim3(D_ / G2N, B_ / G2M), 256, gemm2_smem>>>();
    k_out<<<(B_ * W_ * D_ / 8) / 256, 256>>>(x, out);
}